// round 16
// baseline (speedup 1.0000x reference)
#include <cuda_runtime.h>
#include <cuda_fp16.h>
#include <cstdint>
#include <cstddef>

// ---------------------------------------------------------------------------
// Y[4096,11008] = x[4096,4096] @ dequant(W_int8)[11008,4096]^T + bias
//
// Plain-sm_103 PTX only (harness emits compute_103 PTX; tcgen05/cta_group::2
// are 'a'-suffix features and unavailable). Ampere-style pipeline:
//   prologue:  W int8 * group-scale -> fp16 scratch;  x fp32 -> fp16 scratch
//   mainloop:  cp.async 3-stage, ldmatrix + mma.sync.m16n8k16 (fp32 acc)
// Single fp16 pass: input rounding 2^-11 on both operands -> ~4e-4 rel err.
// ---------------------------------------------------------------------------

#define M_TOTAL   4096
#define K_TOTAL   4096
#define N_TOTAL   11008
#define N_GROUPS  32

#define BM        128
#define BN        256
#define BK        64                    // halves per k-step = 128 bytes/row
#define STAGES    3
#define NKT       (K_TOTAL / BK)        // 64

#define A_STAGE_BYTES (BM * 128)        // 16 KB
#define B_STAGE_BYTES (BN * 128)        // 32 KB
#define STAGE_BYTES   (A_STAGE_BYTES + B_STAGE_BYTES)   // 48 KB
#define SMEM_BYTES    (STAGES * STAGE_BYTES)            // 144 KB

#define TILES_M   (M_TOTAL / BM)        // 32
#define TILES_N   (N_TOTAL / BN)        // 43

// -------------------- device scratch (no cudaMalloc allowed) ---------------
__device__ __align__(1024) __half g_wf[(size_t)N_TOTAL * K_TOTAL];  // 90.2 MB
__device__ __align__(1024) __half g_xf[(size_t)M_TOTAL * K_TOTAL];  // 33.5 MB

// ----------------------------- PTX helpers ---------------------------------
__device__ __forceinline__ uint32_t smem_u32(const void* p) {
    uint32_t a;
    asm("{ .reg .u64 t; cvta.to.shared.u64 t, %1; cvt.u32.u64 %0, t; }"
        : "=r"(a) : "l"(p));
    return a;
}
__device__ __forceinline__ void cp_async16(uint32_t dst, const void* src) {
    asm volatile("cp.async.cg.shared.global [%0], [%1], 16;"
                 :: "r"(dst), "l"(src) : "memory");
}
__device__ __forceinline__ void cp_commit() {
    asm volatile("cp.async.commit_group;" ::: "memory");
}
__device__ __forceinline__ void cp_wait1() {
    asm volatile("cp.async.wait_group 1;" ::: "memory");
}
__device__ __forceinline__ void ldmx4(uint32_t* r, uint32_t addr) {
    asm volatile("ldmatrix.sync.aligned.m8n8.x4.shared.b16 {%0,%1,%2,%3}, [%4];"
                 : "=r"(r[0]), "=r"(r[1]), "=r"(r[2]), "=r"(r[3])
                 : "r"(addr));
}
__device__ __forceinline__ void mma16816(float* d, const uint32_t* a,
                                         const uint32_t* b) {
    asm volatile(
        "mma.sync.aligned.m16n8k16.row.col.f32.f16.f16.f32 "
        "{%0,%1,%2,%3}, {%4,%5,%6,%7}, {%8,%9}, {%0,%1,%2,%3};"
        : "+f"(d[0]), "+f"(d[1]), "+f"(d[2]), "+f"(d[3])
        : "r"(a[0]), "r"(a[1]), "r"(a[2]), "r"(a[3]), "r"(b[0]), "r"(b[1]));
}

// ------------------------- prologue kernels --------------------------------
// W_int8 (int32 storage, values 0..126) * per-group fp32 scale -> fp16
__global__ __launch_bounds__(256) void dequant_kernel(
    const int* __restrict__ w, const float* __restrict__ scale) {
    size_t i = ((size_t)blockIdx.x * 256 + threadIdx.x) * 4;
    int4 wi = *reinterpret_cast<const int4*>(w + i);
    size_t o = i >> 12;                 // / 4096
    int    k = (int)(i & 4095);
    float  s = __ldg(scale + o * N_GROUPS + (k >> 7));
    __half2 h0 = __floats2half2_rn((float)wi.x * s, (float)wi.y * s);
    __half2 h1 = __floats2half2_rn((float)wi.z * s, (float)wi.w * s);
    *reinterpret_cast<__half2*>(g_wf + i)     = h0;
    *reinterpret_cast<__half2*>(g_wf + i + 2) = h1;
}

// x fp32 -> fp16
__global__ __launch_bounds__(256) void cvt_kernel(const float* __restrict__ x) {
    size_t i = ((size_t)blockIdx.x * 256 + threadIdx.x) * 4;
    float4 v = *reinterpret_cast<const float4*>(x + i);
    *reinterpret_cast<__half2*>(g_xf + i)     = __floats2half2_rn(v.x, v.y);
    *reinterpret_cast<__half2*>(g_xf + i + 2) = __floats2half2_rn(v.z, v.w);
}

// ----------------------------- main GEMM -----------------------------------
// CTA 128x256x64, 256 threads, 8 warps of 64x64. SW128 swizzled SMEM
// (chunk16 index XOR row&7) -> conflict-free cp.async stores + ldmatrix loads.
__global__ void __launch_bounds__(256, 1)
gemm_kernel(const float* __restrict__ bias, float* __restrict__ out) {
    extern __shared__ char smem[];
    const uint32_t sb = smem_u32(smem);
    const int tid  = threadIdx.x;
    const int lane = tid & 31;
    const int w    = tid >> 5;
    const int wm   = w & 1;             // 2 warp-rows of 64
    const int wn   = w >> 1;            // 4 warp-cols of 64

    const int pid = blockIdx.x;
    const int mt  = pid & 31;           // m fastest -> x stays L2-resident
    const int nt  = pid >> 5;

    // -------- loader mapping: A 4x16B/thr, B 8x16B/thr ---------------------
    const int ar  = tid >> 1;           // A row 0..127
    const int ac0 = (tid & 1) * 4;      // first of 4 chunk16s
    const int br  = tid;                // B row 0..255
    const __half* __restrict__ Aload =
        g_xf + (size_t)(mt * BM + ar) * K_TOTAL + ac0 * 8;
    const __half* __restrict__ Bload =
        g_wf + (size_t)(nt * BN + br) * K_TOTAL;
    const uint32_t aswz = (uint32_t)((ar & 7) << 4);
    const uint32_t bswz = (uint32_t)((br & 7) << 4);
    uint32_t adst[4], bdst[8];
#pragma unroll
    for (int j = 0; j < 4; ++j)
        adst[j] = (uint32_t)ar * 128 + (((uint32_t)(ac0 + j) << 4) ^ aswz);
#pragma unroll
    for (int j = 0; j < 8; ++j)
        bdst[j] = (uint32_t)br * 128 + (((uint32_t)j << 4) ^ bswz)
                  + A_STAGE_BYTES;

    // -------- fragment lane addressing (per-stage offsets) -----------------
    // addr = row*128 + (kbyte ^ ((row&7)<<4)); row&7 == lane&7 for all frags.
    const uint32_t swz = (uint32_t)((lane & 7) << 4);
    const uint32_t ahi = (uint32_t)((lane >> 4) << 4);        // A k-half
    const uint32_t bhi = (uint32_t)(((lane >> 3) & 1) << 4);  // B k-half
    uint32_t rowA[4], rowB[4];
#pragma unroll
    for (int mi = 0; mi < 4; ++mi)
        rowA[mi] = (uint32_t)((wm * 64 + mi * 16 + (lane & 15)) * 128);
#pragma unroll
    for (int p = 0; p < 4; ++p)        // B x4 covers ni = 2p, 2p+1
        rowB[p] = (uint32_t)((wn * 64 + p * 16 + ((lane >> 4) << 3)
                              + (lane & 7)) * 128) + A_STAGE_BYTES;

    float acc[4][8][4];
#pragma unroll
    for (int mi = 0; mi < 4; ++mi)
#pragma unroll
        for (int ni = 0; ni < 8; ++ni)
#pragma unroll
            for (int q = 0; q < 4; ++q) acc[mi][ni][q] = 0.f;

    auto load_stage = [&](int stage, int kt) {
        const uint32_t base = sb + (uint32_t)stage * STAGE_BYTES;
        const __half* Ap = Aload + (size_t)kt * BK;
        const __half* Bp = Bload + (size_t)kt * BK;
#pragma unroll
        for (int j = 0; j < 4; ++j) cp_async16(base + adst[j], Ap + j * 8);
#pragma unroll
        for (int j = 0; j < 8; ++j) cp_async16(base + bdst[j], Bp + j * 8);
    };

    // -------- prologue: fill stages 0,1 ------------------------------------
    load_stage(0, 0); cp_commit();
    load_stage(1, 1); cp_commit();

    // -------- mainloop -----------------------------------------------------
    for (int kt = 0; kt < NKT; ++kt) {
        const int s = kt % STAGES;
        cp_wait1();                  // stage kt landed (<=1 group in flight)
        __syncthreads();             // visible to all warps
        const uint32_t sbase = sb + (uint32_t)s * STAGE_BYTES;
#pragma unroll
        for (int ks = 0; ks < 4; ++ks) {      // 4 x k16 per stage
            uint32_t af[4][4], bf[4][4];
#pragma unroll
            for (int mi = 0; mi < 4; ++mi)
                ldmx4(af[mi], sbase + rowA[mi]
                              + (((uint32_t)(ks << 5) | ahi) ^ swz));
#pragma unroll
            for (int p = 0; p < 4; ++p)
                ldmx4(bf[p], sbase + rowB[p]
                             + (((uint32_t)(ks << 5) | bhi) ^ swz));
#pragma unroll
            for (int mi = 0; mi < 4; ++mi)
#pragma unroll
                for (int ni = 0; ni < 8; ++ni)
                    mma16816(acc[mi][ni], af[mi],
                             &bf[ni >> 1][(ni & 1) * 2]);
        }
        __syncthreads();             // all warps done reading stage s
        if (kt + 2 < NKT) load_stage((kt + 2) % STAGES, kt + 2);
        cp_commit();                 // commit every iter (keeps counts uniform)
    }

    // -------- epilogue: fp32 + bias, float2 stores -------------------------
    const size_t orow0 = (size_t)(mt * BM + wm * 64);
    const int    ocol0 = nt * BN + wn * 64;
    const int    erow  = lane >> 2;
    const int    ecol  = (lane & 3) * 2;
#pragma unroll
    for (int ni = 0; ni < 8; ++ni) {
        const int c = ocol0 + ni * 8 + ecol;
        const float2 bv = *reinterpret_cast<const float2*>(bias + c);
#pragma unroll
        for (int mi = 0; mi < 4; ++mi) {
            const size_t r0 = orow0 + mi * 16 + erow;
            float2 v0 = make_float2(acc[mi][ni][0] + bv.x,
                                    acc[mi][ni][1] + bv.y);
            float2 v1 = make_float2(acc[mi][ni][2] + bv.x,
                                    acc[mi][ni][3] + bv.y);
            *reinterpret_cast<float2*>(out + r0 * N_TOTAL + c)       = v0;
            *reinterpret_cast<float2*>(out + (r0 + 8) * N_TOTAL + c) = v1;
        }
    }
}

// ------------------------------ launcher -----------------------------------
extern "C" void kernel_launch(void* const* d_in, const int* in_sizes, int n_in,
                              void* d_out, int out_size) {
    (void)in_sizes; (void)n_in; (void)out_size;
    const float* x     = (const float*)d_in[0];
    const int*   wq    = (const int*)  d_in[1];
    const float* scale = (const float*)d_in[2];
    const float* bias  = (const float*)d_in[3];
    float* out = (float*)d_out;

    dequant_kernel<<<(unsigned)(((size_t)N_TOTAL * K_TOTAL) / 1024), 256>>>(wq, scale);
    cvt_kernel    <<<(unsigned)(((size_t)M_TOTAL * K_TOTAL) / 1024), 256>>>(x);

    cudaFuncSetAttribute(gemm_kernel,
                         cudaFuncAttributeMaxDynamicSharedMemorySize, SMEM_BYTES);
    gemm_kernel<<<TILES_M * TILES_N, 256, SMEM_BYTES>>>(bias, out);
}

// round 17
// speedup vs baseline: 1.4077x; 1.4077x over previous
#include <cuda_runtime.h>
#include <cuda_fp16.h>
#include <cstdint>
#include <cstddef>

// ---------------------------------------------------------------------------
// Y[4096,11008] = x[4096,4096] @ dequant(W_int8)[11008,4096]^T + bias
//
// Plain-sm_103 PTX (no tcgen05). Ampere-style pipeline, round-16 rework:
//   512 threads / 16 warps (4 per SMSP)  -- was 8 warps, latency-bound
//   CTA tile 256x128, warp tile 64x32
//   4-stage cp.async pipeline, prefetch distance 3, ONE syncthreads per iter
// ---------------------------------------------------------------------------

#define M_TOTAL   4096
#define K_TOTAL   4096
#define N_TOTAL   11008
#define N_GROUPS  32

#define BM        256
#define BN        128
#define BK        64                    // halves per k-step = 128 bytes/row
#define STAGES    4
#define NKT       (K_TOTAL / BK)        // 64

#define A_STAGE_BYTES (BM * 128)        // 32 KB
#define B_STAGE_BYTES (BN * 128)        // 16 KB
#define STAGE_BYTES   (A_STAGE_BYTES + B_STAGE_BYTES)   // 48 KB
#define SMEM_BYTES    (STAGES * STAGE_BYTES)            // 192 KB

#define TILES_M   (M_TOTAL / BM)        // 16
#define TILES_N   (N_TOTAL / BN)        // 86

// -------------------- device scratch (no cudaMalloc allowed) ---------------
__device__ __align__(1024) __half g_wf[(size_t)N_TOTAL * K_TOTAL];  // 90.2 MB
__device__ __align__(1024) __half g_xf[(size_t)M_TOTAL * K_TOTAL];  // 33.5 MB

// ----------------------------- PTX helpers ---------------------------------
__device__ __forceinline__ uint32_t smem_u32(const void* p) {
    uint32_t a;
    asm("{ .reg .u64 t; cvta.to.shared.u64 t, %1; cvt.u32.u64 %0, t; }"
        : "=r"(a) : "l"(p));
    return a;
}
__device__ __forceinline__ void cp_async16(uint32_t dst, const void* src) {
    asm volatile("cp.async.cg.shared.global [%0], [%1], 16;"
                 :: "r"(dst), "l"(src) : "memory");
}
__device__ __forceinline__ void cp_commit() {
    asm volatile("cp.async.commit_group;" ::: "memory");
}
__device__ __forceinline__ void cp_wait2() {
    asm volatile("cp.async.wait_group 2;" ::: "memory");
}
__device__ __forceinline__ void ldmx4(uint32_t* r, uint32_t addr) {
    asm volatile("ldmatrix.sync.aligned.m8n8.x4.shared.b16 {%0,%1,%2,%3}, [%4];"
                 : "=r"(r[0]), "=r"(r[1]), "=r"(r[2]), "=r"(r[3])
                 : "r"(addr));
}
__device__ __forceinline__ void mma16816(float* d, const uint32_t* a,
                                         const uint32_t* b) {
    asm volatile(
        "mma.sync.aligned.m16n8k16.row.col.f32.f16.f16.f32 "
        "{%0,%1,%2,%3}, {%4,%5,%6,%7}, {%8,%9}, {%0,%1,%2,%3};"
        : "+f"(d[0]), "+f"(d[1]), "+f"(d[2]), "+f"(d[3])
        : "r"(a[0]), "r"(a[1]), "r"(a[2]), "r"(a[3]), "r"(b[0]), "r"(b[1]));
}

// ------------------------- prologue kernels --------------------------------
__global__ __launch_bounds__(256) void dequant_kernel(
    const int* __restrict__ w, const float* __restrict__ scale) {
    size_t i = ((size_t)blockIdx.x * 256 + threadIdx.x) * 4;
    int4 wi = *reinterpret_cast<const int4*>(w + i);
    size_t o = i >> 12;                 // / 4096
    int    k = (int)(i & 4095);
    float  s = __ldg(scale + o * N_GROUPS + (k >> 7));
    __half2 h0 = __floats2half2_rn((float)wi.x * s, (float)wi.y * s);
    __half2 h1 = __floats2half2_rn((float)wi.z * s, (float)wi.w * s);
    *reinterpret_cast<__half2*>(g_wf + i)     = h0;
    *reinterpret_cast<__half2*>(g_wf + i + 2) = h1;
}

__global__ __launch_bounds__(256) void cvt_kernel(const float* __restrict__ x) {
    size_t i = ((size_t)blockIdx.x * 256 + threadIdx.x) * 4;
    float4 v = *reinterpret_cast<const float4*>(x + i);
    *reinterpret_cast<__half2*>(g_xf + i)     = __floats2half2_rn(v.x, v.y);
    *reinterpret_cast<__half2*>(g_xf + i + 2) = __floats2half2_rn(v.z, v.w);
}

// ----------------------------- main GEMM -----------------------------------
__global__ void __launch_bounds__(512, 1)
gemm_kernel(const float* __restrict__ bias, float* __restrict__ out) {
    extern __shared__ char smem[];
    const uint32_t sb = smem_u32(smem);
    const int tid  = threadIdx.x;
    const int lane = tid & 31;
    const int w    = tid >> 5;
    const int wm   = w & 3;             // 4 warp-rows of 64
    const int wn   = w >> 2;            // 4 warp-cols of 32

    const int pid = blockIdx.x;
    const int mt  = pid & 15;           // m fastest -> x stays L2-resident
    const int nt  = pid >> 4;

    // -------- loader mapping: A 4x16B/thr, B 2x16B/thr ---------------------
    const int ar  = tid >> 1;           // A row 0..255
    const int ac0 = (tid & 1) * 4;      // first of 4 chunk16s
    const int br  = tid >> 2;           // B row 0..127
    const int bc0 = (tid & 3) * 2;      // first of 2 chunk16s
    const __half* __restrict__ Aload =
        g_xf + (size_t)(mt * BM + ar) * K_TOTAL + ac0 * 8;
    const __half* __restrict__ Bload =
        g_wf + (size_t)(nt * BN + br) * K_TOTAL + bc0 * 8;
    const uint32_t aswz = (uint32_t)((ar & 7) << 4);
    const uint32_t bswz = (uint32_t)((br & 7) << 4);
    uint32_t adst[4], bdst[2];
#pragma unroll
    for (int j = 0; j < 4; ++j)
        adst[j] = (uint32_t)ar * 128 + (((uint32_t)(ac0 + j) << 4) ^ aswz);
#pragma unroll
    for (int j = 0; j < 2; ++j)
        bdst[j] = (uint32_t)br * 128 + (((uint32_t)(bc0 + j) << 4) ^ bswz)
                  + A_STAGE_BYTES;

    // -------- fragment lane addressing -------------------------------------
    const uint32_t swz = (uint32_t)((lane & 7) << 4);
    const uint32_t ahi = (uint32_t)((lane >> 4) << 4);        // A k-half
    const uint32_t bhi = (uint32_t)(((lane >> 3) & 1) << 4);  // B k-half
    uint32_t rowA[4], rowB[2];
#pragma unroll
    for (int mi = 0; mi < 4; ++mi)
        rowA[mi] = (uint32_t)((wm * 64 + mi * 16 + (lane & 15)) * 128);
#pragma unroll
    for (int p = 0; p < 2; ++p)        // B x4 covers ni = 2p, 2p+1
        rowB[p] = (uint32_t)((wn * 32 + p * 16 + ((lane >> 4) << 3)
                              + (lane & 7)) * 128) + A_STAGE_BYTES;

    float acc[4][4][4];
#pragma unroll
    for (int mi = 0; mi < 4; ++mi)
#pragma unroll
        for (int ni = 0; ni < 4; ++ni)
#pragma unroll
            for (int q = 0; q < 4; ++q) acc[mi][ni][q] = 0.f;

    auto load_stage = [&](int stage, int kt) {
        const uint32_t base = sb + (uint32_t)stage * STAGE_BYTES;
        const __half* Ap = Aload + (size_t)kt * BK;
        const __half* Bp = Bload + (size_t)kt * BK;
#pragma unroll
        for (int j = 0; j < 4; ++j) cp_async16(base + adst[j], Ap + j * 8);
#pragma unroll
        for (int j = 0; j < 2; ++j) cp_async16(base + bdst[j], Bp + j * 8);
    };

    // -------- prologue: fill stages 0,1,2 ----------------------------------
    load_stage(0, 0); cp_commit();
    load_stage(1, 1); cp_commit();
    load_stage(2, 2); cp_commit();

    // -------- mainloop: one barrier per iter, loads issued under compute ---
    for (int kt = 0; kt < NKT; ++kt) {
        const int s = kt % STAGES;
        cp_wait2();                  // stage kt landed (<=2 groups in flight)
        __syncthreads();             // stage kt visible; stage kt-1 reads done
        // prefetch stage kt+3 -> buffer (kt+3)%4 == (kt-1)%4, now free
        if (kt + STAGES - 1 < NKT) load_stage((kt + 3) % STAGES, kt + 3);
        cp_commit();                 // commit every iter: uniform accounting

        const uint32_t sbase = sb + (uint32_t)s * STAGE_BYTES;
#pragma unroll
        for (int ks = 0; ks < 4; ++ks) {      // 4 x k16 per stage
            uint32_t af[4][4], bf[2][4];
#pragma unroll
            for (int mi = 0; mi < 4; ++mi)
                ldmx4(af[mi], sbase + rowA[mi]
                              + (((uint32_t)(ks << 5) | ahi) ^ swz));
#pragma unroll
            for (int p = 0; p < 2; ++p)
                ldmx4(bf[p], sbase + rowB[p]
                             + (((uint32_t)(ks << 5) | bhi) ^ swz));
#pragma unroll
            for (int mi = 0; mi < 4; ++mi)
#pragma unroll
                for (int ni = 0; ni < 4; ++ni)
                    mma16816(acc[mi][ni], af[mi],
                             &bf[ni >> 1][(ni & 1) * 2]);
        }
    }

    // -------- epilogue: fp32 + bias, float2 stores -------------------------
    const size_t orow0 = (size_t)(mt * BM + wm * 64);
    const int    ocol0 = nt * BN + wn * 32;
    const int    erow  = lane >> 2;
    const int    ecol  = (lane & 3) * 2;
#pragma unroll
    for (int ni = 0; ni < 4; ++ni) {
        const int c = ocol0 + ni * 8 + ecol;
        const float2 bv = *reinterpret_cast<const float2*>(bias + c);
#pragma unroll
        for (int mi = 0; mi < 4; ++mi) {
            const size_t r0 = orow0 + mi * 16 + erow;
            float2 v0 = make_float2(acc[mi][ni][0] + bv.x,
                                    acc[mi][ni][1] + bv.y);
            float2 v1 = make_float2(acc[mi][ni][2] + bv.x,
                                    acc[mi][ni][3] + bv.y);
            *reinterpret_cast<float2*>(out + r0 * N_TOTAL + c)       = v0;
            *reinterpret_cast<float2*>(out + (r0 + 8) * N_TOTAL + c) = v1;
        }
    }
}

// ------------------------------ launcher -----------------------------------
extern "C" void kernel_launch(void* const* d_in, const int* in_sizes, int n_in,
                              void* d_out, int out_size) {
    (void)in_sizes; (void)n_in; (void)out_size;
    const float* x     = (const float*)d_in[0];
    const int*   wq    = (const int*)  d_in[1];
    const float* scale = (const float*)d_in[2];
    const float* bias  = (const float*)d_in[3];
    float* out = (float*)d_out;

    dequant_kernel<<<(unsigned)(((size_t)N_TOTAL * K_TOTAL) / 1024), 256>>>(wq, scale);
    cvt_kernel    <<<(unsigned)(((size_t)M_TOTAL * K_TOTAL) / 1024), 256>>>(x);

    cudaFuncSetAttribute(gemm_kernel,
                         cudaFuncAttributeMaxDynamicSharedMemorySize, SMEM_BYTES);
    gemm_kernel<<<TILES_M * TILES_N, 512, SMEM_BYTES>>>(bias, out);
}